// round 6
// baseline (speedup 1.0000x reference)
#include <cuda_runtime.h>
#include <cstdint>
#include <math.h>

#define BB 4
#define TT 2048
#define DD 1024
#define MTOT (BB * TT)
#define SCALE (0.03125f)

// ---------------- scratch (no allocations allowed) ----------------
__device__ float g_xr[(size_t)MTOT * DD];      // x rounded to tf32
__device__ float g_wt[(size_t)3 * DD * DD];    // W^T rounded: [n][k]
__device__ float g_q[(size_t)MTOT * DD];       // tf32-rounded
__device__ float g_k[(size_t)MTOT * DD];       // tf32-rounded ([t][e] = B [n][k] for scores)
__device__ float g_v[(size_t)MTOT * DD];       // tf32-rounded
__device__ float g_vt[(size_t)BB * DD * TT];   // V^T per batch [e][t]
__device__ float g_s[(size_t)BB * TT * TT];    // scores -> att (att tf32-rounded)

// ---------------- helpers ----------------
__device__ __forceinline__ uint32_t f2tf(float x) {
    uint32_t u;
    asm("cvt.rna.tf32.f32 %0, %1;" : "=r"(u) : "f"(x));
    return u;
}
__device__ __forceinline__ float roundtf(float x) {
    return __uint_as_float(f2tf(x));
}
__device__ __forceinline__ void mma_tf32(float* c, const uint32_t* a, const uint32_t* b) {
    asm volatile(
        "mma.sync.aligned.m16n8k8.row.col.f32.tf32.tf32.f32 "
        "{%0,%1,%2,%3}, {%4,%5,%6,%7}, {%8,%9}, {%0,%1,%2,%3};"
        : "+f"(c[0]), "+f"(c[1]), "+f"(c[2]), "+f"(c[3])
        : "r"(a[0]), "r"(a[1]), "r"(a[2]), "r"(a[3]), "r"(b[0]), "r"(b[1]));
}
__device__ __forceinline__ uint32_t smem_u32(const void* p) {
    uint32_t a;
    asm("{ .reg .u64 t; cvta.to.shared.u64 t, %1; cvt.u32.u64 %0, t; }" : "=r"(a) : "l"(p));
    return a;
}
__device__ __forceinline__ void ldsm4(uint32_t* r, uint32_t saddr) {
    asm volatile("ldmatrix.sync.aligned.m8n8.x4.shared.b16 {%0,%1,%2,%3}, [%4];"
                 : "=r"(r[0]), "=r"(r[1]), "=r"(r[2]), "=r"(r[3]) : "r"(saddr));
}
__device__ __forceinline__ void cpa16(uint32_t* dst, const float* src) {
    asm volatile("cp.async.cg.shared.global [%0], [%1], 16;"
                 :: "r"(smem_u32(dst)), "l"(src));
}
#define CP_COMMIT() asm volatile("cp.async.commit_group;" ::: "memory")
#define CP_WAIT2()  asm volatile("cp.async.wait_group 2;" ::: "memory")

// Tiles: A [128 m][16 k], B [128 n][16 k] — identical padded layout, stride 20.
// Row stride 20 words -> ldmatrix's 8 rows hit banks {0,20,8,28,16,4,24,12}*4..+3
// = all 32 banks, conflict-free.
#define KC 16
#define STAGES 4
#define SA 20
#define A_WORDS (128 * SA)                 // 2560
#define STAGE_WORDS (2 * A_WORDS)          // 5120
#define SMEM_BYTES (STAGES * STAGE_WORDS * 4)  // 81920

// ---------------------------------------------------------------------------
// 128x128 block GEMM: tf32 mma.sync + ldmatrix fragments + 4-stage cp.async.
//   A: [128, K] row-major (lda)      (M operand, pre-rounded tf32)
//   B: [128, K] row-major (ldb)      (N operand, rows are OUTPUT COLUMNS)
//   C: [128,128] row-major (ldc), scaled; optional tf32 round on store.
// 256 threads, warps 4(M) x 2(N), warp tile 32x64.
// ---------------------------------------------------------------------------
__device__ __forceinline__ void gemm128_lm(
    const float* __restrict__ A, int lda,
    const float* __restrict__ B, int ldb,
    float* __restrict__ C, int ldc,
    int K, float scale, bool round_out)
{
    extern __shared__ uint32_t dsm[];

    const int tid = threadIdx.x;
    const int wid = tid >> 5, lane = tid & 31;
    const int g = lane >> 2, t = lane & 3;
    const int wm = wid & 3;
    const int wn = wid >> 2;

    // cp.async mapping: each thread moves 2 float4 per tile
    const int rowL = tid >> 1;
    const int wordL = (tid & 1) * 4;

    // ldmatrix per-lane address offsets (in words, before *4)
    const uint32_t smem0 = smem_u32(dsm);
    const int a_off = (wm * 32 + (lane & 15)) * SA + (lane >> 4) * 4;
    const int b_off = (wn * 64 + (lane >> 4) * 8 + (lane & 7)) * SA + ((lane >> 3) & 1) * 4;

    float acc[2][8][4];
#pragma unroll
    for (int mi = 0; mi < 2; mi++)
#pragma unroll
        for (int ni = 0; ni < 8; ni++)
#pragma unroll
            for (int j = 0; j < 4; j++) acc[mi][ni][j] = 0.f;

    const int nc = K >> 4;

    auto issue = [&](int c) {
        const int k0 = c * KC;
        uint32_t* st = dsm + (c & (STAGES - 1)) * STAGE_WORDS;
        const float* Ap = A + (size_t)rowL * lda + k0 + wordL;
        cpa16(st + rowL * SA + wordL, Ap);
        cpa16(st + rowL * SA + wordL + 8, Ap + 8);
        const float* Bp = B + (size_t)rowL * ldb + k0 + wordL;
        cpa16(st + A_WORDS + rowL * SA + wordL, Bp);
        cpa16(st + A_WORDS + rowL * SA + wordL + 8, Bp + 8);
    };

    issue(0); CP_COMMIT();
    issue(1); CP_COMMIT();
    issue(2); CP_COMMIT();

    for (int c = 0; c < nc; c++) {
        CP_WAIT2();
        __syncthreads();
        const uint32_t sa = smem0 + ((c & (STAGES - 1)) * STAGE_WORDS) * 4;
        const uint32_t sb = sa + A_WORDS * 4;

#pragma unroll
        for (int ks = 0; ks < KC; ks += 8) {
            uint32_t af[2][4];
            ldsm4(af[0], sa + (a_off + ks) * 4);
            ldsm4(af[1], sa + (a_off + 16 * SA + ks) * 4);
            uint32_t bf[8][2];
#pragma unroll
            for (int nb = 0; nb < 4; nb++) {
                uint32_t br[4];
                ldsm4(br, sb + (b_off + nb * 16 * SA + ks) * 4);
                bf[2 * nb][0] = br[0]; bf[2 * nb][1] = br[1];
                bf[2 * nb + 1][0] = br[2]; bf[2 * nb + 1][1] = br[3];
            }
#pragma unroll
            for (int mi = 0; mi < 2; mi++)
#pragma unroll
                for (int ni = 0; ni < 8; ni++)
                    mma_tf32(acc[mi][ni], af[mi], bf[ni]);
        }

        if (c + 3 < nc) issue(c + 3);
        CP_COMMIT();
    }

    // epilogue: float2 stores
#pragma unroll
    for (int mi = 0; mi < 2; mi++) {
        const int r0 = wm * 32 + mi * 16 + g;
#pragma unroll
        for (int ni = 0; ni < 8; ni++) {
            const int col = wn * 64 + ni * 8 + 2 * t;
            float2 v0, v1;
            if (round_out) {
                v0.x = roundtf(acc[mi][ni][0] * scale); v0.y = roundtf(acc[mi][ni][1] * scale);
                v1.x = roundtf(acc[mi][ni][2] * scale); v1.y = roundtf(acc[mi][ni][3] * scale);
            } else {
                v0.x = acc[mi][ni][0] * scale; v0.y = acc[mi][ni][1] * scale;
                v1.x = acc[mi][ni][2] * scale; v1.y = acc[mi][ni][3] * scale;
            }
            *reinterpret_cast<float2*>(C + (size_t)r0 * ldc + col) = v0;
            *reinterpret_cast<float2*>(C + (size_t)(r0 + 8) * ldc + col) = v1;
        }
    }
}

// ---------------------------------------------------------------------------
// GEMM wrappers (scratch symbols referenced from device code only)
// ---------------------------------------------------------------------------
__global__ void __launch_bounds__(256, 2)
proj_mma()
{
    const int z = blockIdx.z;
    const float* B = g_wt + (size_t)z * DD * DD + (size_t)blockIdx.x * 128 * DD;  // [n][k]
    float* C = ((z == 0) ? g_q : (z == 1) ? g_k : g_v)
             + (size_t)blockIdx.y * 128 * DD + blockIdx.x * 128;
    const float* A = g_xr + (size_t)blockIdx.y * 128 * DD;
    gemm128_lm(A, DD, B, DD, C, DD, DD, 1.0f, true);
}

__global__ void __launch_bounds__(256, 2)
scores_mma()
{
    if (blockIdx.x > blockIdx.y) return;   // fully masked tile
    const int b = blockIdx.z;
    const size_t qb = (size_t)blockIdx.y * 128, kb = (size_t)blockIdx.x * 128;
    const float* A = g_q + (size_t)b * TT * DD + qb * DD;        // [q][e]
    const float* B = g_k + (size_t)b * TT * DD + kb * DD;        // [t][e] = [n][k] !
    float* C = g_s + (size_t)b * TT * TT + qb * TT + kb;
    gemm128_lm(A, DD, B, DD, C, TT, DD, SCALE, false);
}

__global__ void __launch_bounds__(256, 2)
pv_mma(float* __restrict__ out)
{
    const int b = blockIdx.z;
    const size_t qb = (size_t)blockIdx.y * 128, eb = (size_t)blockIdx.x * 128;
    const int kmax = (blockIdx.y + 1) * 128;  // att[q,k]=0 beyond q
    const float* A = g_s + (size_t)b * TT * TT + qb * TT;        // [q][t]
    const float* B = g_vt + (size_t)b * DD * TT + eb * TT;       // [e][t] = [n][k]
    float* C = out + (size_t)b * TT * DD + qb * DD + eb;
    gemm128_lm(A, TT, B, TT, C, DD, kmax, 1.0f, false);
}

// ---------------------------------------------------------------------------
// Pre-rounding passes
// ---------------------------------------------------------------------------
__global__ void __launch_bounds__(256)
round_x_kernel(const float4* __restrict__ src)
{
    const int i = blockIdx.x * 256 + threadIdx.x;   // exact grid
    float4 v = src[i];
    v.x = roundtf(v.x); v.y = roundtf(v.y);
    v.z = roundtf(v.z); v.w = roundtf(v.w);
    reinterpret_cast<float4*>(g_xr)[i] = v;
}

// round W to tf32 AND transpose: W [k][n] -> g_wt [n][k]
__global__ void __launch_bounds__(256)
round_wt_kernel(const float* __restrict__ Wq, const float* __restrict__ Wk,
                const float* __restrict__ Wv)
{
    __shared__ float tbuf[32][33];
    const int z = blockIdx.z;
    const float* W = (z == 0) ? Wq : (z == 1) ? Wk : Wv;
    float* WT = g_wt + (size_t)z * DD * DD;
    const int kb = blockIdx.x * 32, nb = blockIdx.y * 32;
    const int tx = threadIdx.x & 31, ty = threadIdx.x >> 5;
#pragma unroll
    for (int j = 0; j < 4; j++)
        tbuf[ty + 8 * j][tx] = roundtf(W[(size_t)(kb + ty + 8 * j) * DD + nb + tx]);
    __syncthreads();
#pragma unroll
    for (int j = 0; j < 4; j++)
        WT[(size_t)(nb + ty + 8 * j) * DD + kb + tx] = tbuf[tx][ty + 8 * j];
}

// ---------------------------------------------------------------------------
// V transpose per batch: g_v [t][e] -> g_vt [e][t]
// ---------------------------------------------------------------------------
__global__ void __launch_bounds__(256)
transpose_v_kernel()
{
    __shared__ float tbuf[32][33];
    const int b = blockIdx.z;
    const float* V = g_v + (size_t)b * TT * DD;
    float* VT = g_vt + (size_t)b * DD * TT;
    const int tb = blockIdx.x * 32, eb = blockIdx.y * 32;
    const int tx = threadIdx.x & 31, ty = threadIdx.x >> 5;
#pragma unroll
    for (int j = 0; j < 4; j++)
        tbuf[ty + 8 * j][tx] = V[(size_t)(tb + ty + 8 * j) * DD + eb + tx];
    __syncthreads();
#pragma unroll
    for (int j = 0; j < 4; j++)
        VT[(size_t)(eb + ty + 8 * j) * TT + tb + tx] = tbuf[tx][ty + 8 * j];
}

// ---------------------------------------------------------------------------
// Causal softmax (in-place on g_s); zero-fills k > q; rounds att to tf32.
// ---------------------------------------------------------------------------
__global__ void __launch_bounds__(256)
softmax_kernel()
{
    const int row = blockIdx.x;  // b*TT + q
    const int q = row % TT;
    float* s = g_s + (size_t)row * TT;
    const int n = q + 1;
    const int tid = threadIdx.x;
    __shared__ float red[256];

    float vals[8];
    float m = -INFINITY;
#pragma unroll
    for (int i = 0; i < 8; i++) {
        const int idx = tid + i * 256;
        vals[i] = (idx < n) ? s[idx] : -INFINITY;
        m = fmaxf(m, vals[i]);
    }
    red[tid] = m;
    __syncthreads();
    for (int off = 128; off > 0; off >>= 1) {
        if (tid < off) red[tid] = fmaxf(red[tid], red[tid + off]);
        __syncthreads();
    }
    m = red[0];
    __syncthreads();

    float sum = 0.f;
#pragma unroll
    for (int i = 0; i < 8; i++) {
        vals[i] = (tid + i * 256 < n) ? __expf(vals[i] - m) : 0.f;
        sum += vals[i];
    }
    red[tid] = sum;
    __syncthreads();
    for (int off = 128; off > 0; off >>= 1) {
        if (tid < off) red[tid] += red[tid + off];
        __syncthreads();
    }
    const float inv = 1.f / red[0];
#pragma unroll
    for (int i = 0; i < 8; i++)
        s[tid + i * 256] = roundtf(vals[i] * inv);
}

// ---------------------------------------------------------------------------
extern "C" void kernel_launch(void* const* d_in, const int* in_sizes, int n_in,
                              void* d_out, int out_size)
{
    const float* x  = (const float*)d_in[0];
    const float* Wq = (const float*)d_in[1];
    const float* Wk = (const float*)d_in[2];
    const float* Wv = (const float*)d_in[3];
    float* out = (float*)d_out;

    cudaFuncSetAttribute(proj_mma,   cudaFuncAttributeMaxDynamicSharedMemorySize, SMEM_BYTES);
    cudaFuncSetAttribute(scores_mma, cudaFuncAttributeMaxDynamicSharedMemorySize, SMEM_BYTES);
    cudaFuncSetAttribute(pv_mma,     cudaFuncAttributeMaxDynamicSharedMemorySize, SMEM_BYTES);

    // 0) pre-round x; round+transpose W
    round_x_kernel<<<MTOT * DD / 4 / 256, 256>>>((const float4*)x);
    {
        dim3 grid(DD / 32, DD / 32, 3);
        round_wt_kernel<<<grid, 256>>>(Wq, Wk, Wv);
    }
    {   // 1) QKV projections (epilogue rounds Q/K/V to tf32)
        dim3 grid(DD / 128, MTOT / 128, 3);
        proj_mma<<<grid, 256, SMEM_BYTES>>>();
    }
    {   // 2) V^T
        dim3 grid(TT / 32, DD / 32, BB);
        transpose_v_kernel<<<grid, 256>>>();
    }
    {   // 3) scores = scale * Q K^T (causal block skip; K used directly as [n][k])
        dim3 grid(TT / 128, TT / 128, BB);
        scores_mma<<<grid, 256, SMEM_BYTES>>>();
    }
    // 4) softmax (rounds att to tf32)
    softmax_kernel<<<MTOT, 256>>>();
    {   // 5) out = att V
        dim3 grid(DD / 128, TT / 128, BB);
        pv_mma<<<grid, 256, SMEM_BYTES>>>(out);
    }
}

// round 7
// speedup vs baseline: 1.1410x; 1.1410x over previous
#include <cuda_runtime.h>
#include <cstdint>
#include <math.h>

#define BB 4
#define TT 2048
#define DD 1024
#define MTOT (BB * TT)
#define SCALE (0.03125f)

// ---------------- scratch (no allocations allowed) ----------------
__device__ float g_xr[(size_t)MTOT * DD];      // x rounded to tf32
__device__ float g_wr[(size_t)3 * DD * DD];    // W rounded: [k][n]
__device__ float g_q[(size_t)MTOT * DD];       // tf32-rounded
__device__ float g_k[(size_t)MTOT * DD];       // tf32-rounded
__device__ float g_v[(size_t)MTOT * DD];       // tf32-rounded
__device__ float g_kt[(size_t)BB * DD * TT];   // K^T per batch [e][t]
__device__ float g_s[(size_t)BB * TT * TT];    // scores -> att (att tf32-rounded)

// ---------------- helpers ----------------
__device__ __forceinline__ uint32_t f2tf(float x) {
    uint32_t u;
    asm("cvt.rna.tf32.f32 %0, %1;" : "=r"(u) : "f"(x));
    return u;
}
__device__ __forceinline__ float roundtf(float x) {
    return __uint_as_float(f2tf(x));
}
__device__ __forceinline__ void mma_tf32(float* c, const uint32_t* a, const uint32_t* b) {
    asm volatile(
        "mma.sync.aligned.m16n8k8.row.col.f32.tf32.tf32.f32 "
        "{%0,%1,%2,%3}, {%4,%5,%6,%7}, {%8,%9}, {%0,%1,%2,%3};"
        : "+f"(c[0]), "+f"(c[1]), "+f"(c[2]), "+f"(c[3])
        : "r"(a[0]), "r"(a[1]), "r"(a[2]), "r"(a[3]), "r"(b[0]), "r"(b[1]));
}
__device__ __forceinline__ uint32_t smem_u32(const void* p) {
    uint32_t a;
    asm("{ .reg .u64 t; cvta.to.shared.u64 t, %1; cvt.u32.u64 %0, t; }" : "=r"(a) : "l"(p));
    return a;
}
__device__ __forceinline__ void cpa16(uint32_t* dst, const float* src) {
    asm volatile("cp.async.cg.shared.global [%0], [%1], 16;"
                 :: "r"(smem_u32(dst)), "l"(src));
}
#define CP_COMMIT() asm volatile("cp.async.commit_group;" ::: "memory")
#define CP_WAIT1()  asm volatile("cp.async.wait_group 1;" ::: "memory")

// CTA tile 128(M) x 256(N), KC=16, 3-stage cp.async.
// A tile [128 m][16 k] stride 20; B tile [16 k][256 n] stride 264.
// Bank checks: A frag word = r*20 + t -> g*20+t covers all 32 banks.
//              B frag word = t*264 + cc -> t*8+g covers all 32 banks.
#define KC 16
#define STAGES 3
#define SA 20
#define SB 264
#define A_WORDS (128 * SA)                 // 2560
#define B_WORDS (KC * SB)                  // 4224
#define STAGE_WORDS (A_WORDS + B_WORDS)    // 6784
#define SMEM_BYTES (STAGES * STAGE_WORDS * 4)  // 81408

// ---------------------------------------------------------------------------
// 128x256 block GEMM via tf32 mma.sync + cp.async 3-stage pipeline.
//   A: [128, K] row-major (lda).  B: [K, 256] row-major (ldb).
//   Inputs PRE-ROUNDED to tf32 (raw-bit feed).
//   C: [128, 256] row-major (ldc), scaled; optional tf32 round on store.
// 256 threads: warps 2(M) x 4(N), warp tile 64x64.
// ---------------------------------------------------------------------------
__device__ __forceinline__ void gemm256_cp(
    const float* __restrict__ A, int lda,
    const float* __restrict__ B, int ldb,
    float* __restrict__ C, int ldc,
    int K, float scale, bool round_out)
{
    extern __shared__ uint32_t dsm[];

    const int tid = threadIdx.x;
    const int wid = tid >> 5, lane = tid & 31;
    const int g = lane >> 2, t = lane & 3;
    const int wm = wid & 1;          // 64 rows each
    const int wn = wid >> 1;         // 64 cols each

    // cp.async mappings
    const int rowA = tid >> 2;            // 0..63 (and +64)
    const int kqA = (tid & 3) * 4;        // word 0/4/8/12
    const int rowB = tid >> 6;            // 0..3 (then +4, +8, +12)
    const int nqB = (tid & 63) * 4;       // word col

    float acc[4][8][4];
#pragma unroll
    for (int mi = 0; mi < 4; mi++)
#pragma unroll
        for (int ni = 0; ni < 8; ni++)
#pragma unroll
            for (int j = 0; j < 4; j++) acc[mi][ni][j] = 0.f;

    const int nc = K >> 4;

    auto issue = [&](int c) {
        const int k0 = c * KC;
        uint32_t* st = dsm + (c % STAGES) * STAGE_WORDS;
        cpa16(st + rowA * SA + kqA, A + (size_t)rowA * lda + k0 + kqA);
        cpa16(st + (rowA + 64) * SA + kqA, A + (size_t)(rowA + 64) * lda + k0 + kqA);
        uint32_t* bt = st + A_WORDS;
#pragma unroll
        for (int r = 0; r < 4; r++)
            cpa16(bt + (rowB + 4 * r) * SB + nqB,
                  B + (size_t)(k0 + rowB + 4 * r) * ldb + nqB);
    };

    issue(0); CP_COMMIT();
    issue(1); CP_COMMIT();

    for (int c = 0; c < nc; c++) {
        CP_WAIT1();
        __syncthreads();
        const uint32_t* As = dsm + (c % STAGES) * STAGE_WORDS;
        const uint32_t* Bs = As + A_WORDS;

#pragma unroll
        for (int ks = 0; ks < KC; ks += 8) {
            uint32_t af[4][4];
#pragma unroll
            for (int mi = 0; mi < 4; mi++) {
                const int r = wm * 64 + mi * 16 + g;
                af[mi][0] = As[r * SA + ks + t];
                af[mi][1] = As[(r + 8) * SA + ks + t];
                af[mi][2] = As[r * SA + ks + t + 4];
                af[mi][3] = As[(r + 8) * SA + ks + t + 4];
            }
            uint32_t bf[8][2];
#pragma unroll
            for (int ni = 0; ni < 8; ni++) {
                const int cc = wn * 64 + ni * 8 + g;
                bf[ni][0] = Bs[(ks + t) * SB + cc];
                bf[ni][1] = Bs[(ks + t + 4) * SB + cc];
            }
#pragma unroll
            for (int mi = 0; mi < 4; mi++)
#pragma unroll
                for (int ni = 0; ni < 8; ni++)
                    mma_tf32(acc[mi][ni], af[mi], bf[ni]);
        }

        if (c + 2 < nc) issue(c + 2);
        CP_COMMIT();
    }

    // epilogue: float2 stores
#pragma unroll
    for (int mi = 0; mi < 4; mi++) {
        const int r0 = wm * 64 + mi * 16 + g;
#pragma unroll
        for (int ni = 0; ni < 8; ni++) {
            const int col = wn * 64 + ni * 8 + 2 * t;
            float2 v0, v1;
            if (round_out) {
                v0.x = roundtf(acc[mi][ni][0] * scale); v0.y = roundtf(acc[mi][ni][1] * scale);
                v1.x = roundtf(acc[mi][ni][2] * scale); v1.y = roundtf(acc[mi][ni][3] * scale);
            } else {
                v0.x = acc[mi][ni][0] * scale; v0.y = acc[mi][ni][1] * scale;
                v1.x = acc[mi][ni][2] * scale; v1.y = acc[mi][ni][3] * scale;
            }
            *reinterpret_cast<float2*>(C + (size_t)r0 * ldc + col) = v0;
            *reinterpret_cast<float2*>(C + (size_t)(r0 + 8) * ldc + col) = v1;
        }
    }
}

// ---------------------------------------------------------------------------
// GEMM wrappers (scratch symbols referenced from device code only)
// ---------------------------------------------------------------------------
__global__ void __launch_bounds__(256, 1)
proj_mma()
{
    const int z = blockIdx.z;
    const float* W = g_wr + (size_t)z * DD * DD;                    // [k][n]
    float* C = ((z == 0) ? g_q : (z == 1) ? g_k : g_v)
             + (size_t)blockIdx.y * 128 * DD + blockIdx.x * 256;
    const float* A = g_xr + (size_t)blockIdx.y * 128 * DD;
    gemm256_cp(A, DD, W + blockIdx.x * 256, DD, C, DD, DD, 1.0f, true);
}

__global__ void __launch_bounds__(256, 1)
scores_mma()
{
    if (2 * blockIdx.x > blockIdx.y) return;   // fully masked 128x256 tile
    const int b = blockIdx.z;
    const size_t qb = (size_t)blockIdx.y * 128, kb = (size_t)blockIdx.x * 256;
    const float* A = g_q + (size_t)b * TT * DD + qb * DD;     // [q][e]
    const float* B = g_kt + (size_t)b * DD * TT + kb;         // [e][t]
    float* C = g_s + (size_t)b * TT * TT + qb * TT + kb;
    gemm256_cp(A, DD, B, TT, C, TT, DD, SCALE, false);
}

__global__ void __launch_bounds__(256, 1)
pv_mma(float* __restrict__ out)
{
    const int b = blockIdx.z;
    const size_t qb = (size_t)blockIdx.y * 128, eb = (size_t)blockIdx.x * 256;
    const int kmax = (blockIdx.y + 1) * 128;  // att[q,k]=0 beyond q
    const float* A = g_s + (size_t)b * TT * TT + qb * TT;     // [q][t]
    const float* B = g_v + (size_t)b * TT * DD + eb;          // [t][e]
    float* C = out + (size_t)b * TT * DD + qb * DD + eb;
    gemm256_cp(A, TT, B, DD, C, DD, kmax, 1.0f, false);
}

// ---------------------------------------------------------------------------
// tf32 pre-rounding passes (device-symbol destinations named in device code)
// ---------------------------------------------------------------------------
__global__ void __launch_bounds__(256)
round_x_kernel(const float4* __restrict__ src)
{
    const int i = blockIdx.x * 256 + threadIdx.x;   // exact grid
    float4 v = src[i];
    v.x = roundtf(v.x); v.y = roundtf(v.y);
    v.z = roundtf(v.z); v.w = roundtf(v.w);
    reinterpret_cast<float4*>(g_xr)[i] = v;
}

__global__ void __launch_bounds__(256)
round_w_kernel(const float4* __restrict__ Wq, const float4* __restrict__ Wk,
               const float4* __restrict__ Wv)
{
    const int n4 = DD * DD / 4;
    const int i = blockIdx.x * 256 + threadIdx.x;   // exact grid
    const int z = blockIdx.y;
    const float4* src = (z == 0) ? Wq : (z == 1) ? Wk : Wv;
    float4 v = src[i];
    v.x = roundtf(v.x); v.y = roundtf(v.y);
    v.z = roundtf(v.z); v.w = roundtf(v.w);
    reinterpret_cast<float4*>(g_wr)[(size_t)z * n4 + i] = v;
}

// ---------------------------------------------------------------------------
// K transpose per batch: g_k [t][e] -> g_kt [e][t]
// ---------------------------------------------------------------------------
__global__ void __launch_bounds__(256)
transpose_k_kernel()
{
    __shared__ float tbuf[32][33];
    const int b = blockIdx.z;
    const float* Km = g_k + (size_t)b * TT * DD;
    float* KT = g_kt + (size_t)b * DD * TT;
    const int tb = blockIdx.x * 32, eb = blockIdx.y * 32;
    const int tx = threadIdx.x & 31, ty = threadIdx.x >> 5;
#pragma unroll
    for (int j = 0; j < 4; j++)
        tbuf[ty + 8 * j][tx] = Km[(size_t)(tb + ty + 8 * j) * DD + eb + tx];
    __syncthreads();
#pragma unroll
    for (int j = 0; j < 4; j++)
        KT[(size_t)(eb + ty + 8 * j) * TT + tb + tx] = tbuf[tx][ty + 8 * j];
}

// ---------------------------------------------------------------------------
// Causal softmax (in-place on g_s); zero-fills k > q; rounds att to tf32.
// ---------------------------------------------------------------------------
__global__ void __launch_bounds__(256)
softmax_kernel()
{
    const int row = blockIdx.x;  // b*TT + q
    const int q = row % TT;
    float* s = g_s + (size_t)row * TT;
    const int n = q + 1;
    const int tid = threadIdx.x;
    __shared__ float red[256];

    float vals[8];
    float m = -INFINITY;
#pragma unroll
    for (int i = 0; i < 8; i++) {
        const int idx = tid + i * 256;
        vals[i] = (idx < n) ? s[idx] : -INFINITY;
        m = fmaxf(m, vals[i]);
    }
    red[tid] = m;
    __syncthreads();
    for (int off = 128; off > 0; off >>= 1) {
        if (tid < off) red[tid] = fmaxf(red[tid], red[tid + off]);
        __syncthreads();
    }
    m = red[0];
    __syncthreads();

    float sum = 0.f;
#pragma unroll
    for (int i = 0; i < 8; i++) {
        vals[i] = (tid + i * 256 < n) ? __expf(vals[i] - m) : 0.f;
        sum += vals[i];
    }
    red[tid] = sum;
    __syncthreads();
    for (int off = 128; off > 0; off >>= 1) {
        if (tid < off) red[tid] += red[tid + off];
        __syncthreads();
    }
    const float inv = 1.f / red[0];
#pragma unroll
    for (int i = 0; i < 8; i++)
        s[tid + i * 256] = roundtf(vals[i] * inv);
}

// ---------------------------------------------------------------------------
extern "C" void kernel_launch(void* const* d_in, const int* in_sizes, int n_in,
                              void* d_out, int out_size)
{
    const float* x  = (const float*)d_in[0];
    const float* Wq = (const float*)d_in[1];
    const float* Wk = (const float*)d_in[2];
    const float* Wv = (const float*)d_in[3];
    float* out = (float*)d_out;

    cudaFuncSetAttribute(proj_mma,   cudaFuncAttributeMaxDynamicSharedMemorySize, SMEM_BYTES);
    cudaFuncSetAttribute(scores_mma, cudaFuncAttributeMaxDynamicSharedMemorySize, SMEM_BYTES);
    cudaFuncSetAttribute(pv_mma,     cudaFuncAttributeMaxDynamicSharedMemorySize, SMEM_BYTES);

    // 0) pre-round x and W to tf32 (rna)
    round_x_kernel<<<MTOT * DD / 4 / 256, 256>>>((const float4*)x);
    {
        dim3 grid(DD * DD / 4 / 256, 3);
        round_w_kernel<<<grid, 256>>>((const float4*)Wq, (const float4*)Wk,
                                      (const float4*)Wv);
    }
    {   // 1) QKV projections (epilogue rounds Q/K/V to tf32)
        dim3 grid(DD / 256, MTOT / 128, 3);
        proj_mma<<<grid, 256, SMEM_BYTES>>>();
    }
    {   // 2) K^T
        dim3 grid(TT / 32, DD / 32, BB);
        transpose_k_kernel<<<grid, 256>>>();
    }
    {   // 3) scores = scale * Q K^T (causal block skip)
        dim3 grid(TT / 256, TT / 128, BB);
        scores_mma<<<grid, 256, SMEM_BYTES>>>();
    }
    // 4) softmax (rounds att to tf32)
    softmax_kernel<<<MTOT, 256>>>();
    {   // 5) out = att V
        dim3 grid(DD / 256, TT / 128, BB);
        pv_mma<<<grid, 256, SMEM_BYTES>>>(out);
    }
}

// round 8
// speedup vs baseline: 1.1840x; 1.0377x over previous
#include <cuda_runtime.h>
#include <cstdint>
#include <math.h>

#define BB 4
#define TT 2048
#define DD 1024
#define MTOT (BB * TT)
#define SCALE (0.03125f)

// ---------------- scratch (no allocations allowed) ----------------
__device__ float g_xr[(size_t)MTOT * DD];      // x rounded to tf32
__device__ float g_wr[(size_t)3 * DD * DD];    // W rounded: [k][n]
__device__ float g_q[(size_t)MTOT * DD];       // tf32-rounded
__device__ float g_k[(size_t)MTOT * DD];       // tf32-rounded
__device__ float g_v[(size_t)MTOT * DD];       // tf32-rounded
__device__ float g_kt[(size_t)BB * DD * TT];   // K^T per batch [e][t]
__device__ float g_s[(size_t)BB * TT * TT];    // scores -> att (att tf32-rounded)

// ---------------- helpers ----------------
__device__ __forceinline__ uint32_t f2tf(float x) {
    uint32_t u;
    asm("cvt.rna.tf32.f32 %0, %1;" : "=r"(u) : "f"(x));
    return u;
}
__device__ __forceinline__ float roundtf(float x) {
    return __uint_as_float(f2tf(x));
}
__device__ __forceinline__ void mma_tf32(float* c, const uint32_t* a, const uint32_t* b) {
    asm volatile(
        "mma.sync.aligned.m16n8k8.row.col.f32.tf32.tf32.f32 "
        "{%0,%1,%2,%3}, {%4,%5,%6,%7}, {%8,%9}, {%0,%1,%2,%3};"
        : "+f"(c[0]), "+f"(c[1]), "+f"(c[2]), "+f"(c[3])
        : "r"(a[0]), "r"(a[1]), "r"(a[2]), "r"(a[3]), "r"(b[0]), "r"(b[1]));
}
__device__ __forceinline__ uint32_t smem_u32(const void* p) {
    uint32_t a;
    asm("{ .reg .u64 t; cvta.to.shared.u64 t, %1; cvt.u32.u64 %0, t; }" : "=r"(a) : "l"(p));
    return a;
}
__device__ __forceinline__ void cpa16(uint32_t* dst, const float* src) {
    asm volatile("cp.async.cg.shared.global [%0], [%1], 16;"
                 :: "r"(smem_u32(dst)), "l"(src));
}
#define CP_COMMIT() asm volatile("cp.async.commit_group;" ::: "memory")
#define CP_WAIT1()  asm volatile("cp.async.wait_group 1;" ::: "memory")

// SMEM strides (words), conflict-free for fragment loads (validated R3/R5):
#define KC 16
#define STAGES 3
#define SA 20          // A tile: 128 rows x 16 words, row stride 20
#define SB 136         // B tile: 16 rows x 128 words, row stride 136
#define A_WORDS (128 * SA)                 // 2560
#define B_WORDS (KC * SB)                  // 2176
#define STAGE_WORDS (A_WORDS + B_WORDS)    // 4736
#define SMEM_BYTES (STAGES * STAGE_WORDS * 4)  // 56832

// ---------------------------------------------------------------------------
// 128x128 block GEMM via tf32 mma.sync + cp.async 3-stage pipeline.
// (R5 winner — unchanged.)
//   A: [128, K] row-major (lda).  B: [K, 128] row-major (ldb).
//   Inputs PRE-ROUNDED to tf32 (raw-bit feed).
//   C: [128,128] row-major (ldc), scaled; optional tf32 round on store.
// 256 threads, warps 4(M) x 2(N), warp tile 32x64.
// ---------------------------------------------------------------------------
__device__ __forceinline__ void gemm128_cp(
    const float* __restrict__ A, int lda,
    const float* __restrict__ B, int ldb,
    float* __restrict__ C, int ldc,
    int K, float scale, bool round_out)
{
    extern __shared__ uint32_t dsm[];

    const int tid = threadIdx.x;
    const int wid = tid >> 5, lane = tid & 31;
    const int g = lane >> 2, t = lane & 3;
    const int wm = wid & 3;
    const int wn = wid >> 2;

    const int rowA = tid >> 2;
    const int kqA = (tid & 3) * 4;
    const int rowB = tid >> 5;
    const int nqB = (tid & 31) * 4;

    float acc[2][8][4];
#pragma unroll
    for (int mi = 0; mi < 2; mi++)
#pragma unroll
        for (int ni = 0; ni < 8; ni++)
#pragma unroll
            for (int j = 0; j < 4; j++) acc[mi][ni][j] = 0.f;

    const int nc = K >> 4;

    auto issue = [&](int c) {
        const int k0 = c * KC;
        uint32_t* st = dsm + (c % STAGES) * STAGE_WORDS;
        cpa16(st + rowA * SA + kqA, A + (size_t)rowA * lda + k0 + kqA);
        cpa16(st + (rowA + 64) * SA + kqA, A + (size_t)(rowA + 64) * lda + k0 + kqA);
        uint32_t* bt = st + A_WORDS;
        cpa16(bt + rowB * SB + nqB, B + (size_t)(k0 + rowB) * ldb + nqB);
        cpa16(bt + (rowB + 8) * SB + nqB, B + (size_t)(k0 + rowB + 8) * ldb + nqB);
    };

    issue(0); CP_COMMIT();
    issue(1); CP_COMMIT();

    for (int c = 0; c < nc; c++) {
        CP_WAIT1();
        __syncthreads();
        const uint32_t* As = dsm + (c % STAGES) * STAGE_WORDS;
        const uint32_t* Bs = As + A_WORDS;

#pragma unroll
        for (int ks = 0; ks < KC; ks += 8) {
            uint32_t af[2][4];
#pragma unroll
            for (int mi = 0; mi < 2; mi++) {
                const int r = wm * 32 + mi * 16 + g;
                af[mi][0] = As[r * SA + ks + t];
                af[mi][1] = As[(r + 8) * SA + ks + t];
                af[mi][2] = As[r * SA + ks + t + 4];
                af[mi][3] = As[(r + 8) * SA + ks + t + 4];
            }
            uint32_t bf[8][2];
#pragma unroll
            for (int ni = 0; ni < 8; ni++) {
                const int cc = wn * 64 + ni * 8 + g;
                bf[ni][0] = Bs[(ks + t) * SB + cc];
                bf[ni][1] = Bs[(ks + t + 4) * SB + cc];
            }
#pragma unroll
            for (int mi = 0; mi < 2; mi++)
#pragma unroll
                for (int ni = 0; ni < 8; ni++)
                    mma_tf32(acc[mi][ni], af[mi], bf[ni]);
        }

        if (c + 2 < nc) issue(c + 2);
        CP_COMMIT();
    }

#pragma unroll
    for (int mi = 0; mi < 2; mi++) {
        const int r0 = wm * 32 + mi * 16 + g;
#pragma unroll
        for (int ni = 0; ni < 8; ni++) {
            const int col = wn * 64 + ni * 8 + 2 * t;
            float2 v0, v1;
            if (round_out) {
                v0.x = roundtf(acc[mi][ni][0] * scale); v0.y = roundtf(acc[mi][ni][1] * scale);
                v1.x = roundtf(acc[mi][ni][2] * scale); v1.y = roundtf(acc[mi][ni][3] * scale);
            } else {
                v0.x = acc[mi][ni][0] * scale; v0.y = acc[mi][ni][1] * scale;
                v1.x = acc[mi][ni][2] * scale; v1.y = acc[mi][ni][3] * scale;
            }
            *reinterpret_cast<float2*>(C + (size_t)r0 * ldc + col) = v0;
            *reinterpret_cast<float2*>(C + (size_t)(r0 + 8) * ldc + col) = v1;
        }
    }
}

// ---------------------------------------------------------------------------
// GEMM wrappers (scratch symbols referenced from device code only)
// ---------------------------------------------------------------------------
__global__ void __launch_bounds__(256, 2)
proj_mma()
{
    const int z = blockIdx.z;
    const float* W = g_wr + (size_t)z * DD * DD;
    float* C = ((z == 0) ? g_q : (z == 1) ? g_k : g_v)
             + (size_t)blockIdx.y * 128 * DD + blockIdx.x * 128;
    const float* A = g_xr + (size_t)blockIdx.y * 128 * DD;
    gemm128_cp(A, DD, W + blockIdx.x * 128, DD, C, DD, DD, 1.0f, true);
}

__global__ void __launch_bounds__(256, 2)
scores_mma()
{
    if (blockIdx.x > blockIdx.y) return;   // fully masked tile
    const int b = blockIdx.z;
    const size_t qb = (size_t)blockIdx.y * 128, kb = (size_t)blockIdx.x * 128;
    const float* A = g_q + (size_t)b * TT * DD + qb * DD;     // [q][e]
    const float* B = g_kt + (size_t)b * DD * TT + kb;         // [e][t]
    float* C = g_s + (size_t)b * TT * TT + qb * TT + kb;
    gemm128_cp(A, DD, B, TT, C, TT, DD, SCALE, false);
}

__global__ void __launch_bounds__(256, 2)
pv_mma(float* __restrict__ out)
{
    const int b = blockIdx.z;
    const size_t qb = (size_t)blockIdx.y * 128, eb = (size_t)blockIdx.x * 128;
    const int kmax = (blockIdx.y + 1) * 128;  // att[q,k]=0 beyond q
    const float* A = g_s + (size_t)b * TT * TT + qb * TT;     // [q][t]
    const float* B = g_v + (size_t)b * TT * DD + eb;          // [t][e]
    float* C = out + (size_t)b * TT * DD + qb * DD + eb;
    gemm128_cp(A, TT, B, DD, C, DD, kmax, 1.0f, false);
}

// ---------------------------------------------------------------------------
// Merged tf32 pre-rounding: blocks [0, XB) round x; [XB, XB+3*WB) round W.
// ---------------------------------------------------------------------------
#define XB (MTOT * DD / 4 / 256)   // 8192 blocks
#define WBK (DD * DD / 4 / 256)    // 1024 blocks per W
__global__ void __launch_bounds__(256)
round_all_kernel(const float4* __restrict__ x,
                 const float4* __restrict__ Wq, const float4* __restrict__ Wk,
                 const float4* __restrict__ Wv)
{
    const int bi = blockIdx.x;
    if (bi < XB) {
        const int i = bi * 256 + threadIdx.x;
        float4 v = x[i];
        v.x = roundtf(v.x); v.y = roundtf(v.y);
        v.z = roundtf(v.z); v.w = roundtf(v.w);
        reinterpret_cast<float4*>(g_xr)[i] = v;
    } else {
        const int r = bi - XB;
        const int z = r / WBK;
        const int i = (r % WBK) * 256 + threadIdx.x;
        const float4* src = (z == 0) ? Wq : (z == 1) ? Wk : Wv;
        float4 v = src[i];
        v.x = roundtf(v.x); v.y = roundtf(v.y);
        v.z = roundtf(v.z); v.w = roundtf(v.w);
        reinterpret_cast<float4*>(g_wr)[(size_t)z * (DD * DD / 4) + i] = v;
    }
}

// ---------------------------------------------------------------------------
// K transpose per batch (float4 both directions): g_k [t][e] -> g_kt [e][t]
// 64x64 tiles, 256 threads.
// ---------------------------------------------------------------------------
__global__ void __launch_bounds__(256)
transpose_k_kernel()
{
    __shared__ float tbuf[64][65];
    const int b = blockIdx.z;
    const float* Km = g_k + (size_t)b * TT * DD;
    float* KT = g_kt + (size_t)b * DD * TT;
    const int tb = blockIdx.x * 64, eb = blockIdx.y * 64;
    const int c4 = threadIdx.x & 15;        // float4 index (16 per 64-wide row)
    const int r0 = threadIdx.x >> 4;        // 0..15

#pragma unroll
    for (int j = 0; j < 4; j++) {
        const int r = r0 + j * 16;          // t-local 0..63
        float4 v = *reinterpret_cast<const float4*>(
            &Km[(size_t)(tb + r) * DD + eb + c4 * 4]);
        tbuf[r][c4 * 4 + 0] = v.x;
        tbuf[r][c4 * 4 + 1] = v.y;
        tbuf[r][c4 * 4 + 2] = v.z;
        tbuf[r][c4 * 4 + 3] = v.w;
    }
    __syncthreads();
#pragma unroll
    for (int j = 0; j < 4; j++) {
        const int er = r0 + j * 16;         // e-local 0..63
        float4 v;
        v.x = tbuf[c4 * 4 + 0][er];
        v.y = tbuf[c4 * 4 + 1][er];
        v.z = tbuf[c4 * 4 + 2][er];
        v.w = tbuf[c4 * 4 + 3][er];
        *reinterpret_cast<float4*>(&KT[(size_t)(eb + er) * TT + tb + c4 * 4]) = v;
    }
}

// ---------------------------------------------------------------------------
// Causal softmax, float4 path (in-place on g_s); zero-fills k > q; rounds att.
// ---------------------------------------------------------------------------
__global__ void __launch_bounds__(256)
softmax_kernel()
{
    const int row = blockIdx.x;  // b*TT + q
    const int q = row % TT;
    const int n = q + 1;
    float4* s4 = reinterpret_cast<float4*>(g_s + (size_t)row * TT);
    const int tid = threadIdx.x;
    __shared__ float red[256];

    float4 v[2];
    float m = -INFINITY;
#pragma unroll
    for (int i = 0; i < 2; i++) {
        const int idx4 = tid + i * 256;
        v[i] = s4[idx4];
        float* pv = reinterpret_cast<float*>(&v[i]);
        const int base = idx4 * 4;
#pragma unroll
        for (int j = 0; j < 4; j++) {
            if (base + j >= n) pv[j] = -INFINITY;
            else m = fmaxf(m, pv[j]);
        }
    }
    red[tid] = m;
    __syncthreads();
    for (int off = 128; off > 0; off >>= 1) {
        if (tid < off) red[tid] = fmaxf(red[tid], red[tid + off]);
        __syncthreads();
    }
    m = red[0];
    __syncthreads();

    float sum = 0.f;
#pragma unroll
    for (int i = 0; i < 2; i++) {
        float* pv = reinterpret_cast<float*>(&v[i]);
        const int base = (tid + i * 256) * 4;
#pragma unroll
        for (int j = 0; j < 4; j++) {
            const float e = (base + j < n) ? __expf(pv[j] - m) : 0.f;
            pv[j] = e;
            sum += e;
        }
    }
    red[tid] = sum;
    __syncthreads();
    for (int off = 128; off > 0; off >>= 1) {
        if (tid < off) red[tid] += red[tid + off];
        __syncthreads();
    }
    const float inv = 1.f / red[0];
#pragma unroll
    for (int i = 0; i < 2; i++) {
        float* pv = reinterpret_cast<float*>(&v[i]);
        float4 o;
        o.x = roundtf(pv[0] * inv);
        o.y = roundtf(pv[1] * inv);
        o.z = roundtf(pv[2] * inv);
        o.w = roundtf(pv[3] * inv);
        s4[tid + i * 256] = o;
    }
}

// ---------------------------------------------------------------------------
extern "C" void kernel_launch(void* const* d_in, const int* in_sizes, int n_in,
                              void* d_out, int out_size)
{
    const float* x  = (const float*)d_in[0];
    const float* Wq = (const float*)d_in[1];
    const float* Wk = (const float*)d_in[2];
    const float* Wv = (const float*)d_in[3];
    float* out = (float*)d_out;

    cudaFuncSetAttribute(proj_mma,   cudaFuncAttributeMaxDynamicSharedMemorySize, SMEM_BYTES);
    cudaFuncSetAttribute(scores_mma, cudaFuncAttributeMaxDynamicSharedMemorySize, SMEM_BYTES);
    cudaFuncSetAttribute(pv_mma,     cudaFuncAttributeMaxDynamicSharedMemorySize, SMEM_BYTES);

    // 0) pre-round x and W to tf32 (single merged launch)
    round_all_kernel<<<XB + 3 * WBK, 256>>>((const float4*)x, (const float4*)Wq,
                                            (const float4*)Wk, (const float4*)Wv);
    {   // 1) QKV projections (epilogue rounds Q/K/V to tf32)
        dim3 grid(DD / 128, MTOT / 128, 3);
        proj_mma<<<grid, 256, SMEM_BYTES>>>();
    }
    {   // 2) K^T (float4 tiles)
        dim3 grid(TT / 64, DD / 64, BB);
        transpose_k_kernel<<<grid, 256>>>();
    }
    {   // 3) scores = scale * Q K^T (causal block skip)
        dim3 grid(TT / 128, TT / 128, BB);
        scores_mma<<<grid, 256, SMEM_BYTES>>>();
    }
    // 4) softmax (float4, rounds att to tf32)
    softmax_kernel<<<MTOT, 256>>>();
    {   // 5) out = att V
        dim3 grid(DD / 128, TT / 128, BB);
        pv_mma<<<grid, 256, SMEM_BYTES>>>(out);
    }
}